// round 15
// baseline (speedup 1.0000x reference)
#include <cuda_runtime.h>
#include <math.h>

#define S_LEN 512
#define BATCH 64
#define DIN   256
#define H     512
#define G3H   1536          // 3*H
#define SCALE 1.25f         // 1/(1-0.2)
#define NBLK  128           // persistent grid: 32 j-tiles x 4 batch-groups

// dynamic smem: W slice (3*128*16 float4 = 98304 B) + hd (32768 B) + red (26112 B)
#define W_SMEM_F4   (3 * 128 * 16)
#define GRU_SMEM_BYTES (W_SMEM_F4 * 16 + 16 * H * 4 + 8 * 3 * 16 * 17 * 4)  // 157184

// ---------------- packed f32x2 helpers (FFMA2: 2x fp32 per issue, IEEE-exact) ----
struct alignas(16) ULL2 { unsigned long long x, y; };

__device__ __forceinline__ void ffma2(unsigned long long& d,
                                      unsigned long long a, unsigned long long b) {
    asm("fma.rn.f32x2 %0, %1, %2, %0;" : "+l"(d) : "l"(a), "l"(b));
}
__device__ __forceinline__ unsigned long long pack_dup(float a) {
    unsigned long long d; unsigned r = __float_as_uint(a);
    asm("mov.b64 %0, {%1, %1};" : "=l"(d) : "r"(r));
    return d;
}
__device__ __forceinline__ void unpack2(unsigned long long v, float& lo, float& hi) {
    unsigned l, h;
    asm("mov.b64 {%0, %1}, %2;" : "=r"(l), "=r"(h) : "l"(v));
    lo = __uint_as_float(l); hi = __uint_as_float(h);
}
__device__ __forceinline__ float sum2(unsigned long long v) {
    float lo, hi; unpack2(v, lo, hi); return lo + hi;
}

// ---- barrier ops WITHOUT fence instructions (no CCTL.IVALL -> L1 stays warm) ----
__device__ __forceinline__ void bar_arrive_release(unsigned* p) {
    unsigned one = 1u;
    asm volatile("red.release.gpu.global.add.u32 [%0], %1;" :: "l"(p), "r"(one) : "memory");
}
__device__ __forceinline__ unsigned bar_poll_acquire(unsigned* p) {
    unsigned v;
    asm volatile("ld.acquire.gpu.global.u32 %0, [%1];" : "=r"(v) : "l"(p) : "memory");
    return v;
}

// ---------------- scratch (device globals; no cudaMalloc allowed) ----------------
__device__ float g_gi[(size_t)S_LEN * BATCH * G3H];   // 192 MiB, reused both layers
__device__ float g_out0[(size_t)S_LEN * BATCH * H];   // 64 MiB, layer-0 outputs
__device__ float g_h[4][BATCH * H];                   // h double-buffers, per layer
__device__ float4 g_wt[2][3 * 512 * 128];             // 2x 3 MiB transposed W_hh
__device__ unsigned g_bar[8];                         // barrier counters (4 grp x 2 layer)
__device__ unsigned char g_mask[4][BATCH * H];        // canonical uint8 masks

// ---- fused: detect mask transport dtype (per-block, redundant) + convert all 4 ----
__global__ void convert_masks_kernel(const void* __restrict__ m0, const void* __restrict__ m1,
                                     const void* __restrict__ m2, const void* __restrict__ m3,
                                     unsigned char* __restrict__ dst) {
    int f_bf = 0, f_f32 = 0, f_up = 0;
    for (int i = threadIdx.x; i < 1024; i += 256) {
        unsigned w = ((const unsigned*)m0)[i];
        if ((w & 0xFFFFu) == 0x3F80u) f_bf = 1;
        if (w == 0x3F800000u)         f_f32 = 1;
        else if (w != 0u && (w & 0xFFFFFF00u) != 0u && (w & 0xFFFFu) != 0x3F80u) f_up = 1;
    }
    f_bf  = __syncthreads_or(f_bf);
    f_f32 = __syncthreads_or(f_f32);
    f_up  = __syncthreads_or(f_up);
    int code = f_bf ? 3 : (f_f32 ? 2 : (f_up ? 1 : 0)); // 0=int32 1=uint8 2=f32 3=bf16

    int gidx = blockIdx.x * 256 + threadIdx.x;          // 0 .. 114687
    const void* src; int si; unsigned char* d;
    if      (gidx < 16384) { src = m0; si = gidx;          d = dst + si; }
    else if (gidx < 49152) { src = m1; si = gidx - 16384;  d = dst + 32768  + si; }
    else if (gidx < 81920) { src = m2; si = gidx - 49152;  d = dst + 65536  + si; }
    else if (gidx < 114688){ src = m3; si = gidx - 81920;  d = dst + 98304  + si; }
    else return;
    unsigned char v;
    if      (code == 0) v = ((const int*)src)[si] != 0;
    else if (code == 1) v = ((const unsigned char*)src)[si] != 0;
    else if (code == 2) v = ((const float*)src)[si] != 0.f;
    else                v = ((const unsigned short*)src)[si] != 0;
    *d = v;
}

// zero all 4 h buffers + 8 barrier counters
__global__ void reset_kernel(float* hbase) {
    int i = blockIdx.x * blockDim.x + threadIdx.x;
    if (i < 8) g_bar[i] = 0u;
    if (i < 4 * BATCH * H) hbase[i] = 0.f;
}

__global__ void copy_kernel(const float* __restrict__ src, float* __restrict__ dst, int n) {
    int i = blockIdx.x * blockDim.x + threadIdx.x;
    if (i < n) dst[i] = src[i];
}

// ---- transpose W_hh [1536][512] -> Wt[jt 32][g 3][kq 128][jl 16] (float4 per k-quad) ----
__global__ void transpose_w_kernel(const float* __restrict__ w, float4* __restrict__ wt) {
    int idx = blockIdx.x * 256 + threadIdx.x;   // 0 .. 196607
    if (idx >= 3 * 512 * 128) return;
    int jl  = idx & 15;
    int kq  = (idx >> 4) & 127;
    int rem = idx >> 11;                        // 0..95 = jt*3 + g
    int g   = rem % 3;
    int jt  = rem / 3;
    int row = g * H + jt * 16 + jl;
    wt[idx] = *(const float4*)(w + (size_t)row * H + kq * 4);
}

// ---- C[M][1536] = drop(A)[M][K] @ W[1536][K]^T + bias ----
// 128x128x16 tile, 256 threads, 8x8 microtile, f32x2 FMA, double-buffered smem.
__global__ void __launch_bounds__(256, 2) sgemm_mask_bias_kernel(
    const float* __restrict__ A, const unsigned char* __restrict__ mask,
    const float* __restrict__ W, const float* __restrict__ bias,
    float* __restrict__ C, int K)
{
    __shared__ float As[2][16][132];    // +4 pad: bank spread, keeps 16B alignment
    __shared__ float Bs[2][16][132];

    int tid = threadIdx.x;
    int tx = tid % 16;
    int ty = tid / 16;
    int row0 = blockIdx.y * 128;
    int col0 = blockIdx.x * 128;

    int la_r = tid >> 1;          // 0..127 (m or n row)
    int la_c = (tid & 1) * 8;     // k offset 0 or 8

    int arow = row0 + la_r;
    int b    = arow % BATCH;
    const float* Aptr = A + (size_t)arow * K + la_c;
    const unsigned char* Mptr = mask + (size_t)b * K + la_c;
    const float* Wptr = W + (size_t)(col0 + la_r) * K + la_c;

    unsigned long long acc2[8][4];
    #pragma unroll
    for (int i = 0; i < 8; i++)
        #pragma unroll
        for (int j = 0; j < 4; j++) acc2[i][j] = 0ull;

    // preload tile 0
    {
        float4 a0 = *(const float4*)(Aptr);
        float4 a1 = *(const float4*)(Aptr + 4);
        uchar4 q0 = *(const uchar4*)(Mptr);
        uchar4 q1 = *(const uchar4*)(Mptr + 4);
        float4 b0 = *(const float4*)(Wptr);
        float4 b1 = *(const float4*)(Wptr + 4);
        As[0][la_c + 0][la_r] = q0.x ? 0.f : a0.x * SCALE;
        As[0][la_c + 1][la_r] = q0.y ? 0.f : a0.y * SCALE;
        As[0][la_c + 2][la_r] = q0.z ? 0.f : a0.z * SCALE;
        As[0][la_c + 3][la_r] = q0.w ? 0.f : a0.w * SCALE;
        As[0][la_c + 4][la_r] = q1.x ? 0.f : a1.x * SCALE;
        As[0][la_c + 5][la_r] = q1.y ? 0.f : a1.y * SCALE;
        As[0][la_c + 6][la_r] = q1.z ? 0.f : a1.z * SCALE;
        As[0][la_c + 7][la_r] = q1.w ? 0.f : a1.w * SCALE;
        Bs[0][la_c + 0][la_r] = b0.x; Bs[0][la_c + 1][la_r] = b0.y;
        Bs[0][la_c + 2][la_r] = b0.z; Bs[0][la_c + 3][la_r] = b0.w;
        Bs[0][la_c + 4][la_r] = b1.x; Bs[0][la_c + 5][la_r] = b1.y;
        Bs[0][la_c + 6][la_r] = b1.z; Bs[0][la_c + 7][la_r] = b1.w;
    }
    __syncthreads();

    int nt = K / 16;
    for (int t = 0; t < nt; t++) {
        int cur = t & 1, nxt = cur ^ 1;
        float4 pa0, pa1, pb0, pb1; uchar4 pq0, pq1;
        if (t + 1 < nt) {
            int ko = (t + 1) * 16;
            pa0 = *(const float4*)(Aptr + ko);
            pa1 = *(const float4*)(Aptr + ko + 4);
            pq0 = *(const uchar4*)(Mptr + ko);
            pq1 = *(const uchar4*)(Mptr + ko + 4);
            pb0 = *(const float4*)(Wptr + ko);
            pb1 = *(const float4*)(Wptr + ko + 4);
        }
        #pragma unroll
        for (int k = 0; k < 16; k++) {
            float4 af0 = *(const float4*)&As[cur][k][ty * 8];
            float4 af1 = *(const float4*)&As[cur][k][ty * 8 + 4];
            ULL2 bb0 = *(const ULL2*)&Bs[cur][k][tx * 8];
            ULL2 bb1 = *(const ULL2*)&Bs[cur][k][tx * 8 + 4];
            float af[8] = {af0.x, af0.y, af0.z, af0.w, af1.x, af1.y, af1.z, af1.w};
            #pragma unroll
            for (int i = 0; i < 8; i++) {
                unsigned long long a2 = pack_dup(af[i]);
                ffma2(acc2[i][0], a2, bb0.x);
                ffma2(acc2[i][1], a2, bb0.y);
                ffma2(acc2[i][2], a2, bb1.x);
                ffma2(acc2[i][3], a2, bb1.y);
            }
        }
        if (t + 1 < nt) {
            As[nxt][la_c + 0][la_r] = pq0.x ? 0.f : pa0.x * SCALE;
            As[nxt][la_c + 1][la_r] = pq0.y ? 0.f : pa0.y * SCALE;
            As[nxt][la_c + 2][la_r] = pq0.z ? 0.f : pa0.z * SCALE;
            As[nxt][la_c + 3][la_r] = pq0.w ? 0.f : pa0.w * SCALE;
            As[nxt][la_c + 4][la_r] = pq1.x ? 0.f : pa1.x * SCALE;
            As[nxt][la_c + 5][la_r] = pq1.y ? 0.f : pa1.y * SCALE;
            As[nxt][la_c + 6][la_r] = pq1.z ? 0.f : pa1.z * SCALE;
            As[nxt][la_c + 7][la_r] = pq1.w ? 0.f : pa1.w * SCALE;
            Bs[nxt][la_c + 0][la_r] = pb0.x; Bs[nxt][la_c + 1][la_r] = pb0.y;
            Bs[nxt][la_c + 2][la_r] = pb0.z; Bs[nxt][la_c + 3][la_r] = pb0.w;
            Bs[nxt][la_c + 4][la_r] = pb1.x; Bs[nxt][la_c + 5][la_r] = pb1.y;
            Bs[nxt][la_c + 6][la_r] = pb1.z; Bs[nxt][la_c + 7][la_r] = pb1.w;
        }
        __syncthreads();
    }

    #pragma unroll
    for (int i = 0; i < 8; i++) {
        int m = row0 + ty * 8 + i;
        int n = col0 + tx * 8;
        float4 v0, v1;
        unpack2(acc2[i][0], v0.x, v0.y);
        unpack2(acc2[i][1], v0.z, v0.w);
        unpack2(acc2[i][2], v1.x, v1.y);
        unpack2(acc2[i][3], v1.z, v1.w);
        v0.x += bias[n + 0]; v0.y += bias[n + 1];
        v0.z += bias[n + 2]; v0.w += bias[n + 3];
        v1.x += bias[n + 4]; v1.y += bias[n + 5];
        v1.z += bias[n + 6]; v1.w += bias[n + 7];
        *(float4*)&C[(size_t)m * G3H + n]     = v0;
        *(float4*)&C[(size_t)m * G3H + n + 4] = v1;
    }
}

// ---------------- persistent GRU layer: all 512 steps in one launch ----------------
// 128 blocks = 32 j-tiles (16 j) x 4 batch-groups (16 b). 512 threads (16 warps).
// W slice (96 KB) in SMEM; barrier via release/acquire atomics (no L1 flush).
// Critical-path trim: out_s store + next-step gi prefetch execute DURING the
// barrier poll (they don't gate peers).
__global__ void __launch_bounds__(512) gru_layer_kernel(
    float* __restrict__ h_a, float* __restrict__ h_b,
    const float* __restrict__ gi,            // [S][B][3H]
    const float4* __restrict__ wt,           // transposed W_hh
    const float* __restrict__ b_hh,          // [1536]
    const unsigned char* __restrict__ mask_h,// [B][H] canonical uint8
    float* __restrict__ out,                 // [S][B][H]
    unsigned* __restrict__ bar)              // per-group barrier counter base
{
    extern __shared__ float smem_dyn[];
    float4* w_s = (float4*)smem_dyn;                       // [3*128*16] 96 KB
    float*  hd_s = smem_dyn + W_SMEM_F4 * 4;               // [16*H] 32 KB
    float (*red_s)[3][16][17] =
        (float (*)[3][16][17])(hd_s + 16 * H);             // [8][3][16][17] 25.5 KB

    int tid  = threadIdx.x;
    int lane = tid & 31;
    int warp = tid >> 5;
    int jt   = blockIdx.x & 31;
    int grp  = blockIdx.x >> 5;                    // 0..3
    int bbase = grp * 16;

    int bh = warp & 1;                             // batch half (8 b)
    int kw = warp >> 1;                            // 0..7 (64-k slice)
    int jl = lane >> 1;                            // 0..15
    int kh = lane & 1;
    int kwq = kw * 16;                             // first k-quad of slice

    // copy this j-tile's W slice (6144 float4) into smem once
    {
        const float4* wsrc = wt + (size_t)jt * 3 * 128 * 16;
        for (int i = tid; i < W_SMEM_F4; i += 512)
            w_s[i] = wsrc[i];
    }

    // smem W pointers (float4 units), stride 32 float4 per q step
    const float4* wp0 = w_s + ((0 * 128) + kwq + kh) * 16 + jl;
    const float4* wp1 = w_s + ((1 * 128) + kwq + kh) * 16 + jl;
    const float4* wp2 = w_s + ((2 * 128) + kwq + kh) * 16 + jl;

    // epilogue mapping: threads 0..255 -> one (b, j) output each
    int ejl = tid & 15, eb = (tid >> 4) & 15;
    int ej  = jt * 16 + ejl;
    int ebg = bbase + eb;
    float brc = b_hh[ej], bzc = b_hh[H + ej], bnc = b_hh[2 * H + ej];
    const float* gib = gi + (size_t)ebg * G3H;     // advances by B*G3H per step

    const uchar4* mrow4 = (const uchar4*)(mask_h + (size_t)bbase * H);

    unsigned target = 32u;
    unsigned* mybar = bar + grp;

    // prefetch gi for step 0
    float gr = 0.f, gz = 0.f, gn = 0.f;
    if (tid < 256) {
        gr = __ldcg(gib + ej);
        gz = __ldcg(gib + H + ej);
        gn = __ldcg(gib + 2 * H + ej);
    }

    __syncthreads();   // W slice visible

    for (int s = 0; s < S_LEN; s++) {
        const float* h_in  = (s & 1) ? h_b : h_a;
        float*       h_out = (s & 1) ? h_a : h_b;
        float*       out_s = out + (size_t)s * BATCH * H;

        // stage dropped hidden for this group's 16 batches (h via L2: .cg)
        const float4* hrow4 = (const float4*)(h_in + (size_t)bbase * H);
        #pragma unroll
        for (int i = tid; i < 16 * H / 4; i += 512) {
            float4 h4 = __ldcg(hrow4 + i);
            uchar4 m4 = mrow4[i];
            hd_s[i * 4 + 0] = m4.x ? 0.f : h4.x * SCALE;
            hd_s[i * 4 + 1] = m4.y ? 0.f : h4.y * SCALE;
            hd_s[i * 4 + 2] = m4.z ? 0.f : h4.z * SCALE;
            hd_s[i * 4 + 3] = m4.w ? 0.f : h4.w * SCALE;
        }
        __syncthreads();

        unsigned long long acc[3][8];
        #pragma unroll
        for (int g = 0; g < 3; g++)
            #pragma unroll
            for (int b = 0; b < 8; b++) acc[g][b] = 0ull;

        #pragma unroll
        for (int q = 0; q < 8; q++) {
            ULL2 w0 = *(const ULL2*)(wp0 + 32 * q);
            ULL2 w1 = *(const ULL2*)(wp1 + 32 * q);
            ULL2 w2 = *(const ULL2*)(wp2 + 32 * q);
            int koff = (kwq + kh + 2 * q) * 4;
            #pragma unroll
            for (int b = 0; b < 8; b++) {
                ULL2 h2 = *(const ULL2*)&hd_s[(bh * 8 + b) * H + koff];
                ffma2(acc[0][b], h2.x, w0.x); ffma2(acc[0][b], h2.y, w0.y);
                ffma2(acc[1][b], h2.x, w1.x); ffma2(acc[1][b], h2.y, w1.y);
                ffma2(acc[2][b], h2.x, w2.x); ffma2(acc[2][b], h2.y, w2.y);
            }
        }

        // kh-pair reduce via shfl, publish per-kw partials to smem
        #pragma unroll
        for (int g = 0; g < 3; g++)
            #pragma unroll
            for (int b = 0; b < 8; b++) {
                float v = sum2(acc[g][b]);
                v += __shfl_xor_sync(0xFFFFFFFFu, v, 1);
                if (kh == 0) red_s[kw][g][bh * 8 + b][jl] = v;
            }
        __syncthreads();

        // epilogue: threads 0..255, one (b, j) each; sum 8 kw partials.
        // Critical path: store ONLY h_out before the barrier arrive.
        float hnew = 0.f;
        if (tid < 256) {
            float sr = 0.f, sz = 0.f, sn = 0.f;
            #pragma unroll
            for (int w = 0; w < 8; w++) {
                sr += red_s[w][0][eb][ejl];
                sz += red_s[w][1][eb][ejl];
                sn += red_s[w][2][eb][ejl];
            }
            float r = 1.f / (1.f + expf(-(gr + sr + brc)));
            float z = 1.f / (1.f + expf(-(gz + sz + bzc)));
            float n = tanhf(gn + r * (sn + bnc));
            float hd = hd_s[eb * H + ej];
            hnew = (1.f - z) * n + z * hd;
            __stcg(&h_out[(size_t)ebg * H + ej], hnew);
        }

        // ---- group barrier (32 CTAs), release/acquire (NO L1 flush) ----
        __syncthreads();                 // all h_out stores ordered before arrive
        if (tid == 0) bar_arrive_release(mybar);

        // off-critical-path work while the poller spins:
        if (tid < 256) {
            __stcg(&out_s[(size_t)ebg * H + ej], hnew);
            if (s + 1 < S_LEN) {         // prefetch gi for next step
                const float* gib2 = gib + (size_t)(s + 1) * BATCH * G3H;
                gr = __ldcg(gib2 + ej);
                gz = __ldcg(gib2 + H + ej);
                gn = __ldcg(gib2 + 2 * H + ej);
            }
        }
        if (tid == 0) {
            while (bar_poll_acquire(mybar) < target) { }
        }
        __syncthreads();
        target += 32u;
    }
}

// ---------------- launch ----------------
extern "C" void kernel_launch(void* const* d_in, const int* in_sizes, int n_in,
                              void* d_out, int out_size) {
    const float* x     = (const float*)d_in[0];
    const void*  min0  = d_in[1];
    const void*  mh0   = d_in[2];
    const void*  min1  = d_in[3];
    const void*  mh1   = d_in[4];
    const float* w_ih0 = (const float*)d_in[5];
    const float* w_hh0 = (const float*)d_in[6];
    const float* b_ih0 = (const float*)d_in[7];
    const float* b_hh0 = (const float*)d_in[8];
    const float* w_ih1 = (const float*)d_in[9];
    const float* w_hh1 = (const float*)d_in[10];
    const float* b_ih1 = (const float*)d_in[11];
    const float* b_hh1 = (const float*)d_in[12];
    float* out = (float*)d_out;

    float *gi, *out0, *hbuf;
    float4* wt;
    unsigned* bar;
    unsigned char* mbuf;
    cudaGetSymbolAddress((void**)&gi,   g_gi);
    cudaGetSymbolAddress((void**)&out0, g_out0);
    cudaGetSymbolAddress((void**)&hbuf, g_h);
    cudaGetSymbolAddress((void**)&wt,   g_wt);
    cudaGetSymbolAddress((void**)&bar,  g_bar);
    cudaGetSymbolAddress((void**)&mbuf, g_mask);
    const int BH = BATCH * H;                    // 32768
    const size_t WT1 = (size_t)3 * 512 * 128;    // float4 elements per wt buffer
    unsigned char* cmin0 = mbuf;
    unsigned char* cmh0  = mbuf + 32768;
    unsigned char* cmin1 = mbuf + 65536;
    unsigned char* cmh1  = mbuf + 98304;

    const int M = S_LEN * BATCH;                 // 32768
    dim3 gemm_grid(G3H / 128, M / 128);          // (12, 256)

    cudaFuncSetAttribute(gru_layer_kernel,
                         cudaFuncAttributeMaxDynamicSharedMemorySize, GRU_SMEM_BYTES);

    // 1: normalize all masks (fused detect + convert)
    convert_masks_kernel<<<448, 256>>>(min0, mh0, min1, mh1, mbuf);
    // 2: zero h buffers + barrier counters
    reset_kernel<<<(4 * BH + 255) / 256, 256>>>(hbuf);
    // 3-4: both W transposes up front (separate buffers)
    transpose_w_kernel<<<768, 256>>>(w_hh0, wt);
    transpose_w_kernel<<<768, 256>>>(w_hh1, wt + WT1);
    // 5-6: layer 0
    sgemm_mask_bias_kernel<<<gemm_grid, 256>>>(x, cmin0, w_ih0, b_ih0, gi, DIN);
    gru_layer_kernel<<<NBLK, 512, GRU_SMEM_BYTES>>>(hbuf, hbuf + BH, gi,
                                                    wt, b_hh0, cmh0, out0, bar);
    // 7-8: layer 1
    sgemm_mask_bias_kernel<<<gemm_grid, 256>>>(out0, cmin1, w_ih1, b_ih1, gi, H);
    gru_layer_kernel<<<NBLK, 512, GRU_SMEM_BYTES>>>(hbuf + 2 * BH, hbuf + 3 * BH, gi,
                                                    wt + WT1, b_hh1, cmh1, out, bar + 4);
    // 9: h_last == out1[S-1]
    copy_kernel<<<(BH + 255) / 256, 256>>>(out + (size_t)(S_LEN - 1) * BH,
                                           out + (size_t)S_LEN * BH, BH);
}